// round 15
// baseline (speedup 1.0000x reference)
#include <cuda_runtime.h>
#include <cuda_bf16.h>

#define BB 64
#define NQ 300
#define NP 320            // padded column stride (160 u64 pairs)
#define TT 30
#define NH 160            // Hungarian scan threads (5 warps, 1 pair each)
#define BIGF  1e18f
#define HUGEF 1e30f

// per-batch partial sums: [B][3] = {bce_sum, l1_sum, giou_sum}
__device__ float g_partials[BB * 3];
__device__ unsigned g_count;   // zero-init; last block resets each launch

#define BARH() asm volatile("bar.sync 1, 160;" ::: "memory")

// order-isomorphic float <-> u32 key (exact round-trip)
__device__ __forceinline__ unsigned fkey(float f) {
    unsigned b = __float_as_uint(f);
    return b ^ (((unsigned)((int)b >> 31)) | 0x80000000u);
}
__device__ __forceinline__ float funkey(unsigned k) {
    unsigned m = ((unsigned)((int)(~k) >> 31)) | 0x80000000u;
    return __uint_as_float(k ^ m);
}
__device__ __forceinline__ unsigned long long pack2(float x, float y) {
    unsigned long long r; asm("mov.b64 %0,{%1,%2};" : "=l"(r) : "f"(x), "f"(y)); return r;
}
__device__ __forceinline__ void unpack2(unsigned long long v, float& x, float& y) {
    asm("mov.b64 {%0,%1},%2;" : "=f"(x), "=f"(y) : "l"(v));
}
// two independent round-to-nearest f32 adds in one instruction (bit-exact per lane)
__device__ __forceinline__ unsigned long long add2(unsigned long long a, unsigned long long b) {
    unsigned long long r; asm("add.rn.f32x2 %0,%1,%2;" : "=l"(r) : "l"(a), "l"(b)); return r;
}
// pack (key:high32, payload:low32); u64 min == (min key, then min payload)
__device__ __forceinline__ unsigned long long packkj(unsigned key, unsigned p) {
    unsigned long long r; asm("mov.b64 %0,{%1,%2};" : "=l"(r) : "r"(p), "r"(key)); return r;
}
__device__ __forceinline__ unsigned long long umin64(unsigned long long a, unsigned long long b) {
    return a < b ? a : b;
}

__global__ __launch_bounds__(256)
void detr_criterion_kernel(const float* __restrict__ pred_boxes,
                           const float* __restrict__ pred_classes,
                           const float* __restrict__ targets,
                           float* __restrict__ out)
{
    __shared__ __align__(16) float cost[TT * NP];   // [t][n], padded cols zeroed
    __shared__ __align__(16) float4 pb4[NQ];
    __shared__ __align__(16) float4 tg4[TT];
    __shared__ __align__(16) float vneg[NP];        // -v[j]; pads = +1e30 (mask)
    __shared__ __align__(16) float spcfro[NP];      // frozen spc at selection
    __shared__ __align__(16) int2  nxt[NP];         // {path[j], pre-chase col4row[path[j]]}
    __shared__ __align__(16) int   row4col[NQ];
    __shared__ __align__(16) unsigned long long unq[TT];  // {-u[t], -u[t]} packed
    __shared__ unsigned char matched[NQ];
    __shared__ float u[TT];
    __shared__ int   col4row[TT];
    __shared__ int   sorted_idx[TT];
    __shared__ __align__(16) volatile unsigned long long wbest[10];  // 2 parities x 5 warps
    __shared__ float warpsum[8];
    __shared__ float l1s[TT];
    __shared__ float gis[TT];
    __shared__ int   s_last;

    const int b   = blockIdx.x;
    const int tid = threadIdx.x;
    const float* pbg = pred_boxes   + (size_t)b * NQ * 4;
    const float* pc  = pred_classes + (size_t)b * NQ;
    const float* tgg = targets      + (size_t)b * TT * 4;

    // ---- stage boxes in shared (coalesced)
    for (int n = tid; n < NQ; n += blockDim.x) pb4[n] = ((const float4*)pbg)[n];
    if (tid < TT) tg4[tid] = ((const float4*)tgg)[tid];
    __syncthreads();

    // ---- cost matrix (padded): cost[t][n] = -pc[n] - giou + L1
    for (int idx = tid; idx < TT * NP; idx += blockDim.x) {
        int t = idx / NP, n = idx - t * NP;
        float cv = 0.0f;
        if (n < NQ) {
            float4 p = pb4[n];
            float4 g = tg4[t];
            float ax0 = p.x, ay0 = p.y, ax1 = p.x + p.z, ay1 = p.y + p.w;
            float bx0 = g.x, by0 = g.y, bx1 = g.x + g.z, by1 = g.y + g.w;
            float area_a = (ax1 - ax0) * (ay1 - ay0);
            float area_b = (bx1 - bx0) * (by1 - by0);
            float iw = fmaxf(fminf(ax1, bx1) - fmaxf(ax0, bx0), 0.0f);
            float ih = fmaxf(fminf(ay1, by1) - fmaxf(ay0, by0), 0.0f);
            float inter = iw * ih;
            float uni = area_a + area_b - inter;
            float iou = inter / uni;
            float cw = fmaxf(fmaxf(ax1, bx1) - fminf(ax0, bx0), 0.0f);
            float ch = fmaxf(fmaxf(ay1, by1) - fminf(ay0, by0), 0.0f);
            float areac = cw * ch;
            float giou = iou - (areac - uni) / areac;
            float l1 = fabsf(p.x - g.x) + fabsf(p.y - g.y) + fabsf(p.z - g.z) + fabsf(p.w - g.w);
            cv = -pc[n] - giou + l1;
        }
        cost[idx] = cv;
    }
    for (int j = tid; j < NP; j += blockDim.x) vneg[j] = (j < NQ) ? 0.0f : HUGEF;
    for (int j = tid; j < NQ; j += blockDim.x) { row4col[j] = -1; matched[j] = 0; }
    if (tid < TT) { u[tid] = 0.0f; col4row[tid] = -1; unq[tid] = pack2(-0.0f, -0.0f); }
    if (tid < 10) wbest[tid] = 0xFFFFFFFFFFFFFFFFull;   // tag 0x3FFFF > any it
    __syncthreads();

    // ---- Hungarian: ONLY the 5 scanner warps (threads 0..159); warps 5-7 park at bar 0
    if (tid < NH) {
        const int lane = tid & 31;
        const int wid  = tid >> 5;
        const unsigned FULL = 0xffffffffu;
        const unsigned KBIG = fkey(BIGF);
        const unsigned HUGEB = __float_as_uint(HUGEF);
        const bool haveJ = (2 * tid < NQ);   // tid < 150: real columns
        unsigned it = 0;                     // global iteration counter (tag)

        for (int row = 0; row < TT; ++row) {
            // ---- prologue (reads guarded by phase-B barrier of previous row)
            unsigned long long av2;       // packed -v pair; half -> +1e30 once SC'd
            unsigned spk0 = KBIG, spk1 = KBIG;
            int pth0 = 0, pth1 = 0;
            unsigned jr0, jr1;            // payload: (j<<5) | (row4col[j]+1), tag bits 0
            av2 = *(const unsigned long long*)&vneg[2 * tid];
            {
                int r0 = -1, r1 = -1;
                if (haveJ) { r0 = row4col[2 * tid]; r1 = row4col[2 * tid + 1]; }
                jr0 = ((unsigned)(2 * tid)     << 5) | (unsigned)(r0 + 1);
                jr1 = ((unsigned)(2 * tid + 1) << 5) | (unsigned)(r1 + 1);
            }
            unsigned SRmask = 0;
            int   cur_i  = row;
            unsigned long long mv2 = 0;               // pack2(0,0)
            unsigned long long nu2 = unq[row];        // {-u[row], -u[row]}
            float minVal = 0.0f;
            int   sink   = -1;

            while (sink < 0) {
                SRmask |= 1u << cur_i;
                const unsigned long long* crowu =
                    (const unsigned long long*)(cost + cur_i * NP);
                // EXACT ref rounding: ((minVal + c) - u) - v
                unsigned long long r2 = add2(add2(add2(crowu[tid], mv2), nu2), av2);
                float rx, ry; unpack2(r2, rx, ry);
                unsigned kx = fkey(rx), ky = fkey(ry);
                if (kx < spk0) { spk0 = kx; pth0 = cur_i; }
                if (ky < spk1) { spk1 = ky; pth1 = cur_i; }
                unsigned long long best = umin64(packkj(spk0, jr0), packkj(spk1, jr1));
                unsigned bk = (unsigned)(best >> 32), bp = (unsigned)best;
                // per-warp argmin, first-index ties (j in payload bits 5-13, unique)
                unsigned kw_ = __reduce_min_sync(FULL, bk);
                unsigned jc  = (bk == kw_) ? bp : 0xffffffffu;
                unsigned jw  = __reduce_min_sync(FULL, jc);
                const int base = (int)(it & 1u) * 5;
                if (lane == 0) wbest[base + wid] = packkj(kw_, jw | (it << 14));

                // tagged spin-consume (double-buffered; tags monotone -> no ABA)
                unsigned long long c0, c1, c2, c3, c4;
                for (;;) {
                    c0 = wbest[base + 0]; c1 = wbest[base + 1]; c2 = wbest[base + 2];
                    c3 = wbest[base + 3]; c4 = wbest[base + 4];
                    if ((((unsigned)c0 >> 14) == it) & (((unsigned)c1 >> 14) == it) &
                        (((unsigned)c2 >> 14) == it) & (((unsigned)c3 >> 14) == it) &
                        (((unsigned)c4 >> 14) == it)) break;
                }
                unsigned long long g = umin64(umin64(umin64(c0, c1), umin64(c2, c3)), c4);
                ++it;
                unsigned kmin = (unsigned)(g >> 32);
                unsigned pay  = (unsigned)g;
                unsigned jmin = (pay >> 5) & 0x1FFu;
                unsigned rp1  = pay & 31u;
                minVal = funkey(kmin);                 // exact round-trip
                mv2 = pack2(minVal, minVal);

                spcfro[jmin] = minVal;                 // all scanner threads, same value

                // freeze column jmin (owner thread only)
                if (tid == (int)(jmin >> 1)) {
                    if (jmin & 1u) {
                        spk1 = KBIG;
                        av2 = (av2 & 0x00000000FFFFFFFFull) | ((unsigned long long)HUGEB << 32);
                    } else {
                        spk0 = KBIG;
                        av2 = (av2 & 0xFFFFFFFF00000000ull) | (unsigned long long)HUGEB;
                    }
                }

                if (rp1 == 0u) sink = (int)jmin;
                else { cur_i = (int)rp1 - 1; nu2 = unq[cur_i]; }
            }

            // ---- phase A: build nxt links (parallel), dual updates
            {
                nxt[2 * tid]     = make_int2(pth0, col4row[pth0]);
                nxt[2 * tid + 1] = make_int2(pth1, col4row[pth1]);
                float ax, ay; unpack2(av2, ax, ay); int j0 = 2 * tid;
                if (j0     < NQ && ax == HUGEF) vneg[j0]     += minVal - spcfro[j0];
                if (j0 + 1 < NQ && ay == HUGEF) vneg[j0 + 1] += minVal - spcfro[j0 + 1];
            }
            if (tid < TT) {
                if (tid == row) u[tid] += minVal;
                else if ((SRmask >> tid) & 1u) u[tid] += minVal - spcfro[col4row[tid]];
                unq[tid] = pack2(-u[tid], -u[tid]);
            }
            BARH();   // nxt + dual updates complete before chase

            // ---- phase B: augment along alternating path (serial, thread 0)
            if (tid == 0) {
                int j = sink;
                for (;;) {
                    int2 e = nxt[j];
                    row4col[j] = e.x;
                    col4row[e.x] = j;
                    if (e.x == row) break;
                    j = e.y;
                }
            }
            BARH();   // row4col/col4row visible for next prologue
        }

        // boxes_idx = sort(col4row); mark matched set
        if (tid == 0) {
            for (int i = 0; i < TT; ++i) sorted_idx[i] = col4row[i];
            for (int i = 1; i < TT; ++i) {
                int key = sorted_idx[i];
                int k = i - 1;
                while (k >= 0 && sorted_idx[k] > key) { sorted_idx[k + 1] = sorted_idx[k]; --k; }
                sorted_idx[k + 1] = key;
            }
            for (int i = 0; i < TT; ++i) matched[sorted_idx[i]] = 1;
        }
    }
    __syncthreads();

    // ---- BCE over all N queries
    float local = 0.0f;
    for (int n = tid; n < NQ; n += blockDim.x) {
        float p = pc[n];
        float lg = matched[n] ? logf(p) : logf(1.0f - p);
        local += -fmaxf(lg, -100.0f);
    }
    #pragma unroll
    for (int off = 16; off; off >>= 1)
        local += __shfl_down_sync(0xffffffffu, local, off);
    if ((tid & 31) == 0) warpsum[tid >> 5] = local;

    // ---- L1 + GIoU on matched (sorted-index) pairs
    if (tid < TT) {
        int t = tid;
        int n = sorted_idx[t];
        float4 p = pb4[n];
        float4 g = tg4[t];
        l1s[t] = fabsf(p.x - g.x) + fabsf(p.y - g.y) + fabsf(p.z - g.z) + fabsf(p.w - g.w);

        float ax0 = p.x, ay0 = p.y, ax1 = p.x + p.z, ay1 = p.y + p.w;
        float bx0 = g.x, by0 = g.y, bx1 = g.x + g.z, by1 = g.y + g.w;
        float area_a = (ax1 - ax0) * (ay1 - ay0);
        float area_b = (bx1 - bx0) * (by1 - by0);
        float iw = fmaxf(fminf(ax1, bx1) - fmaxf(ax0, bx0), 0.0f);
        float ih = fmaxf(fminf(ay1, by1) - fmaxf(ay0, by0), 0.0f);
        float inter = iw * ih;
        float uni = area_a + area_b - inter;
        float iou = inter / uni;
        float cw = fmaxf(fmaxf(ax1, bx1) - fminf(ax0, bx0), 0.0f);
        float ch = fmaxf(fmaxf(ay1, by1) - fminf(ay0, by0), 0.0f);
        float areac = cw * ch;
        float giou = iou - (areac - uni) / areac;
        gis[t] = 1.0f - giou;
    }
    __syncthreads();

    // ---- per-batch partials + last-block final reduction (deterministic order)
    if (tid == 0) {
        float bce = 0.0f;
        #pragma unroll
        for (int w = 0; w < 8; ++w) bce += warpsum[w];
        float l1 = 0.0f, gi = 0.0f;
        for (int t = 0; t < TT; ++t) { l1 += l1s[t]; gi += gis[t]; }
        g_partials[b * 3 + 0] = bce;
        g_partials[b * 3 + 1] = l1;
        g_partials[b * 3 + 2] = gi;
        __threadfence();
        unsigned ticket = atomicAdd(&g_count, 1u);
        s_last = (ticket == BB - 1) ? 1 : 0;
    }
    __syncthreads();

    if (s_last) {
        __threadfence();
        if (tid < 3) {
            float s = 0.0f;
            for (int bb2 = 0; bb2 < BB; ++bb2) s += g_partials[bb2 * 3 + tid];
            float denom = (tid == 0) ? (float)(BB * NQ) : (float)(BB * TT);
            out[tid] = s / denom;
        }
        if (tid == 0) g_count = 0;   // reset for next graph replay
    }
}

extern "C" void kernel_launch(void* const* d_in, const int* in_sizes, int n_in,
                              void* d_out, int out_size)
{
    const float* pred_boxes = nullptr;
    const float* pred_classes = nullptr;
    const float* targets = nullptr;
    for (int i = 0; i < n_in; ++i) {
        if (in_sizes[i] == BB * NQ * 4)      pred_boxes   = (const float*)d_in[i];
        else if (in_sizes[i] == BB * NQ)     pred_classes = (const float*)d_in[i];
        else if (in_sizes[i] == BB * TT * 4) targets      = (const float*)d_in[i];
    }
    detr_criterion_kernel<<<BB, 256>>>(pred_boxes, pred_classes, targets, (float*)d_out);
}

// round 16
// speedup vs baseline: 1.0046x; 1.0046x over previous
#include <cuda_runtime.h>
#include <cuda_bf16.h>

#define BB 64
#define NQ 300
#define NP 320            // padded column stride (160 u64 pairs)
#define TT 30
#define NH 160            // Hungarian scan threads (5 warps, 1 pair each)
#define BIGF  1e18f
#define HUGEF 1e30f

// per-batch partial sums: [B][3] = {bce_sum, l1_sum, giou_sum}
__device__ float g_partials[BB * 3];
__device__ unsigned g_count;   // zero-init; last block resets each launch

// order-isomorphic float <-> u32 key (exact round-trip)
__device__ __forceinline__ unsigned fkey(float f) {
    unsigned b = __float_as_uint(f);
    return b ^ (((unsigned)((int)b >> 31)) | 0x80000000u);
}
__device__ __forceinline__ unsigned key_bits(unsigned k) {  // float bits of funkey(k)
    return k ^ (((unsigned)((int)(~k) >> 31)) | 0x80000000u);
}
__device__ __forceinline__ unsigned long long pack2(float x, float y) {
    unsigned long long r; asm("mov.b64 %0,{%1,%2};" : "=l"(r) : "f"(x), "f"(y)); return r;
}
__device__ __forceinline__ void unpack2(unsigned long long v, float& x, float& y) {
    asm("mov.b64 {%0,%1},%2;" : "=f"(x), "=f"(y) : "l"(v));
}
// two independent round-to-nearest f32 adds in one instruction (bit-exact per lane)
__device__ __forceinline__ unsigned long long add2(unsigned long long a, unsigned long long b) {
    unsigned long long r; asm("add.rn.f32x2 %0,%1,%2;" : "=l"(r) : "l"(a), "l"(b)); return r;
}
// pack (key:high32, payload:low32); u64 min == (min key, then min payload)
__device__ __forceinline__ unsigned long long packkj(unsigned key, unsigned p) {
    unsigned long long r; asm("mov.b64 %0,{%1,%2};" : "=l"(r) : "r"(p), "r"(key)); return r;
}
__device__ __forceinline__ unsigned long long umin64(unsigned long long a, unsigned long long b) {
    return a < b ? a : b;
}

__global__ __launch_bounds__(256)
void detr_criterion_kernel(const float* __restrict__ pred_boxes,
                           const float* __restrict__ pred_classes,
                           const float* __restrict__ targets,
                           float* __restrict__ out)
{
    __shared__ __align__(16) float cost[TT * NP];   // [t][n], padded cols zeroed
    __shared__ __align__(16) float4 pb4[NQ];
    __shared__ __align__(16) float4 tg4[TT];
    __shared__ __align__(16) float vneg[NP];        // -v[j]; pads = +1e30 (mask)
    __shared__ __align__(16) float spcfro[NP];      // frozen spc at selection
    __shared__ __align__(16) int2  nxt[NP];         // {path[j], pre-chase col4row[path[j]]}
    __shared__ __align__(16) int   row4col[NQ];
    __shared__ __align__(16) unsigned long long unq[TT];  // {-u[t], -u[t]} packed
    __shared__ float corr[NQ];                      // clip(log1p)-clip(logp) per query
    __shared__ float u[TT];
    __shared__ int   col4row[TT];
    __shared__ int   sorted_idx[TT];
    __shared__ __align__(64) unsigned long long wbest[16];  // 2 parities x 8 slots
    __shared__ float basewarp[8];
    __shared__ float corrs[TT];
    __shared__ float l1s[TT];
    __shared__ float gis[TT];
    __shared__ int   s_last;

    const int b   = blockIdx.x;
    const int tid = threadIdx.x;
    const float* pbg = pred_boxes   + (size_t)b * NQ * 4;
    const float* pc  = pred_classes + (size_t)b * NQ;
    const float* tgg = targets      + (size_t)b * TT * 4;

    // ---- stage boxes in shared (coalesced) + BCE precompute
    for (int n = tid; n < NQ; n += blockDim.x) pb4[n] = ((const float4*)pbg)[n];
    if (tid < TT) tg4[tid] = ((const float4*)tgg)[tid];
    {
        float local_base = 0.0f;
        for (int n = tid; n < NQ; n += blockDim.x) {
            float p = pc[n];
            float lgp = fmaxf(logf(p), -100.0f);
            float lg1 = fmaxf(logf(1.0f - p), -100.0f);
            corr[n] = lg1 - lgp;          // matched correction
            local_base += -lg1;           // unmatched base term
        }
        #pragma unroll
        for (int off = 16; off; off >>= 1)
            local_base += __shfl_down_sync(0xffffffffu, local_base, off);
        if ((tid & 31) == 0) basewarp[tid >> 5] = local_base;
    }
    __syncthreads();

    // ---- cost matrix (padded): cost[t][n] = -pc[n] - giou + L1
    for (int idx = tid; idx < TT * NP; idx += blockDim.x) {
        int t = idx / NP, n = idx - t * NP;
        float cv = 0.0f;
        if (n < NQ) {
            float4 p = pb4[n];
            float4 g = tg4[t];
            float ax0 = p.x, ay0 = p.y, ax1 = p.x + p.z, ay1 = p.y + p.w;
            float bx0 = g.x, by0 = g.y, bx1 = g.x + g.z, by1 = g.y + g.w;
            float area_a = (ax1 - ax0) * (ay1 - ay0);
            float area_b = (bx1 - bx0) * (by1 - by0);
            float iw = fmaxf(fminf(ax1, bx1) - fmaxf(ax0, bx0), 0.0f);
            float ih = fmaxf(fminf(ay1, by1) - fmaxf(ay0, by0), 0.0f);
            float inter = iw * ih;
            float uni = area_a + area_b - inter;
            float iou = inter / uni;
            float cw = fmaxf(fmaxf(ax1, bx1) - fminf(ax0, bx0), 0.0f);
            float ch = fmaxf(fmaxf(ay1, by1) - fminf(ay0, by0), 0.0f);
            float areac = cw * ch;
            float giou = iou - (areac - uni) / areac;
            float l1 = fabsf(p.x - g.x) + fabsf(p.y - g.y) + fabsf(p.z - g.z) + fabsf(p.w - g.w);
            cv = -pc[n] - giou + l1;
        }
        cost[idx] = cv;
    }
    for (int j = tid; j < NP; j += blockDim.x) vneg[j] = (j < NQ) ? 0.0f : HUGEF;
    for (int j = tid; j < NQ; j += blockDim.x) row4col[j] = -1;
    if (tid < TT) { u[tid] = 0.0f; col4row[tid] = -1; unq[tid] = pack2(-0.0f, -0.0f); }
    if (tid < 16) wbest[tid] = 0xFFFFFFFFFFFFFFFFull;   // pad slots stay max forever
    __syncthreads();

    // ---- Hungarian: all 8 warps run loop control; threads 0..159 scan (1 pair each)
    {
        const int lane = tid & 31;
        const int wid  = tid >> 5;
        const unsigned FULL = 0xffffffffu;
        const unsigned KBIG = fkey(BIGF);
        const unsigned HUGEB = __float_as_uint(HUGEF);
        const bool scanner = (tid < NH);
        const bool haveJ   = (2 * tid < NQ);   // tid < 150: real columns
        int par = 0;                           // wbest parity (uniform)

        for (int row = 0; row < TT; ++row) {
            // ---- prologue (reads guarded by phase-B barrier of previous row)
            unsigned long long av2 = 0;   // packed -v pair; half -> +1e30 once SC'd
            unsigned spk0 = KBIG, spk1 = KBIG;
            int pth0 = 0, pth1 = 0;
            unsigned jr0 = 0, jr1 = 0;    // payload: (j<<5) | (row4col[j]+1)
            unsigned long long best01 = 0xFFFFFFFFFFFFFFFFull;
            if (scanner) {
                av2 = *(const unsigned long long*)&vneg[2 * tid];
                int r0 = -1, r1 = -1;
                if (haveJ) { r0 = row4col[2 * tid]; r1 = row4col[2 * tid + 1]; }
                jr0 = ((unsigned)(2 * tid)     << 5) | (unsigned)(r0 + 1);
                jr1 = ((unsigned)(2 * tid + 1) << 5) | (unsigned)(r1 + 1);
                best01 = umin64(packkj(KBIG, jr0), packkj(KBIG, jr1));
            }
            unsigned SRmask = 0;
            int   cur_i  = row;
            unsigned long long mv2 = 0;               // pack2(0,0) (0.0f bits = 0)
            unsigned long long nu2 = unq[row];        // {-u[row], -u[row]}
            float minVal = 0.0f;
            int   sink   = -1;

            while (sink < 0) {
                SRmask |= 1u << cur_i;
                if (scanner) {
                    const unsigned long long* crowu =
                        (const unsigned long long*)(cost + cur_i * NP);
                    // EXACT ref rounding: ((minVal + c) - u) - v
                    unsigned long long r2 = add2(add2(add2(crowu[tid], mv2), nu2), av2);
                    float rx, ry; unpack2(r2, rx, ry);
                    unsigned kx = fkey(rx), ky = fkey(ry);
                    // critical path: pack this iter's candidates straight into best01
                    best01 = umin64(best01, umin64(packkj(kx, jr0), packkj(ky, jr1)));
                    unsigned bk = (unsigned)(best01 >> 32), bp = (unsigned)best01;
                    // off-critical bookkeeping for duals/path
                    if (kx < spk0) { spk0 = kx; pth0 = cur_i; }
                    if (ky < spk1) { spk1 = ky; pth1 = cur_i; }
                    // per-warp argmin, first-index ties (j in payload bits 5-13, unique)
                    unsigned kw_ = __reduce_min_sync(FULL, bk);
                    unsigned jc  = (bk == kw_) ? bp : 0xffffffffu;
                    unsigned jw  = __reduce_min_sync(FULL, jc);
                    if (lane == 0) wbest[par * 8 + wid] = packkj(kw_, jw);
                }
                __syncthreads();
                ulonglong2 w01 = *(const ulonglong2*)&wbest[par * 8];
                ulonglong2 w23 = *(const ulonglong2*)&wbest[par * 8 + 2];
                ulonglong2 w45 = *(const ulonglong2*)&wbest[par * 8 + 4];  // .y = pad(max)
                unsigned long long g = umin64(umin64(umin64(w01.x, w01.y),
                                                     umin64(w23.x, w23.y)),
                                              umin64(w45.x, w45.y));
                par ^= 1;
                unsigned kmin = (unsigned)(g >> 32);
                unsigned pay  = (unsigned)g;
                unsigned jmin = pay >> 5;
                unsigned rp1  = pay & 31u;
                unsigned mbits = key_bits(kmin);       // exact float bits of minVal
                mv2 = packkj(mbits, mbits);
                minVal = __uint_as_float(mbits);

                spcfro[jmin] = minVal;                 // all threads, same value

                // freeze column jmin (owner thread only) + restore best01 invariant
                if (tid == (int)(jmin >> 1)) {
                    if (jmin & 1u) {
                        spk1 = KBIG;
                        av2 = (av2 & 0x00000000FFFFFFFFull) | ((unsigned long long)HUGEB << 32);
                    } else {
                        spk0 = KBIG;
                        av2 = (av2 & 0xFFFFFFFF00000000ull) | (unsigned long long)HUGEB;
                    }
                    best01 = umin64(packkj(spk0, jr0), packkj(spk1, jr1));
                }

                if (rp1 == 0u) sink = (int)jmin;
                else { cur_i = (int)rp1 - 1; nu2 = unq[cur_i]; }
            }

            // ---- phase A: build nxt links (parallel), dual updates
            if (scanner) {
                nxt[2 * tid]     = make_int2(pth0, col4row[pth0]);
                nxt[2 * tid + 1] = make_int2(pth1, col4row[pth1]);
                float ax, ay; unpack2(av2, ax, ay); int j0 = 2 * tid;
                if (j0     < NQ && ax == HUGEF) vneg[j0]     += minVal - spcfro[j0];
                if (j0 + 1 < NQ && ay == HUGEF) vneg[j0 + 1] += minVal - spcfro[j0 + 1];
            }
            if (tid < TT) {
                if (tid == row) u[tid] += minVal;
                else if ((SRmask >> tid) & 1u) u[tid] += minVal - spcfro[col4row[tid]];
                unq[tid] = pack2(-u[tid], -u[tid]);
            }
            __syncthreads();   // nxt + dual updates complete before chase

            // ---- phase B: augment along alternating path (serial, thread 0)
            if (tid == 0) {
                int j = sink;
                for (;;) {
                    int2 e = nxt[j];
                    row4col[j] = e.x;
                    col4row[e.x] = j;
                    if (e.x == row) break;
                    j = e.y;
                }
            }
            __syncthreads();   // row4col/col4row visible for next prologue
        }

        // boxes_idx = sort(col4row)
        if (tid == 0) {
            for (int i = 0; i < TT; ++i) sorted_idx[i] = col4row[i];
            for (int i = 1; i < TT; ++i) {
                int key = sorted_idx[i];
                int k = i - 1;
                while (k >= 0 && sorted_idx[k] > key) { sorted_idx[k + 1] = sorted_idx[k]; --k; }
                sorted_idx[k + 1] = key;
            }
        }
    }
    __syncthreads();

    // ---- L1 + GIoU on matched (sorted-index) pairs; BCE corrections
    if (tid < TT) {
        int t = tid;
        int n = sorted_idx[t];
        corrs[t] = corr[n];
        float4 p = pb4[n];
        float4 g = tg4[t];
        l1s[t] = fabsf(p.x - g.x) + fabsf(p.y - g.y) + fabsf(p.z - g.z) + fabsf(p.w - g.w);

        float ax0 = p.x, ay0 = p.y, ax1 = p.x + p.z, ay1 = p.y + p.w;
        float bx0 = g.x, by0 = g.y, bx1 = g.x + g.z, by1 = g.y + g.w;
        float area_a = (ax1 - ax0) * (ay1 - ay0);
        float area_b = (bx1 - bx0) * (by1 - by0);
        float iw = fmaxf(fminf(ax1, bx1) - fmaxf(ax0, bx0), 0.0f);
        float ih = fmaxf(fminf(ay1, by1) - fmaxf(ay0, by0), 0.0f);
        float inter = iw * ih;
        float uni = area_a + area_b - inter;
        float iou = inter / uni;
        float cw = fmaxf(fmaxf(ax1, bx1) - fminf(ax0, bx0), 0.0f);
        float ch = fmaxf(fmaxf(ay1, by1) - fminf(ay0, by0), 0.0f);
        float areac = cw * ch;
        float giou = iou - (areac - uni) / areac;
        gis[t] = 1.0f - giou;
    }
    __syncthreads();

    // ---- per-batch partials + last-block final reduction (deterministic order)
    if (tid == 0) {
        float bce = 0.0f;
        #pragma unroll
        for (int w = 0; w < 8; ++w) bce += basewarp[w];
        for (int t = 0; t < TT; ++t) bce += corrs[t];
        float l1 = 0.0f, gi = 0.0f;
        for (int t = 0; t < TT; ++t) { l1 += l1s[t]; gi += gis[t]; }
        g_partials[b * 3 + 0] = bce;
        g_partials[b * 3 + 1] = l1;
        g_partials[b * 3 + 2] = gi;
        __threadfence();
        unsigned ticket = atomicAdd(&g_count, 1u);
        s_last = (ticket == BB - 1) ? 1 : 0;
    }
    __syncthreads();

    if (s_last) {
        __threadfence();
        if (tid < 3) {
            float s = 0.0f;
            for (int bb2 = 0; bb2 < BB; ++bb2) s += g_partials[bb2 * 3 + tid];
            float denom = (tid == 0) ? (float)(BB * NQ) : (float)(BB * TT);
            out[tid] = s / denom;
        }
        if (tid == 0) g_count = 0;   // reset for next graph replay
    }
}

extern "C" void kernel_launch(void* const* d_in, const int* in_sizes, int n_in,
                              void* d_out, int out_size)
{
    const float* pred_boxes = nullptr;
    const float* pred_classes = nullptr;
    const float* targets = nullptr;
    for (int i = 0; i < n_in; ++i) {
        if (in_sizes[i] == BB * NQ * 4)      pred_boxes   = (const float*)d_in[i];
        else if (in_sizes[i] == BB * NQ)     pred_classes = (const float*)d_in[i];
        else if (in_sizes[i] == BB * TT * 4) targets      = (const float*)d_in[i];
    }
    detr_criterion_kernel<<<BB, 256>>>(pred_boxes, pred_classes, targets, (float*)d_out);
}

// round 17
// speedup vs baseline: 1.0052x; 1.0006x over previous
#include <cuda_runtime.h>
#include <cuda_bf16.h>

#define BB 64
#define NQ 300
#define NP 320            // padded column stride (160 u64 pairs)
#define TT 30
#define NH 160            // Hungarian scan threads (5 warps, 1 pair each)
#define BIGF  1e18f
#define HUGEF 1e30f

// per-batch partial sums: [B][3] = {bce_sum, l1_sum, giou_sum}
__device__ float g_partials[BB * 3];
__device__ unsigned g_count;   // zero-init; last block resets each launch

// order-isomorphic float <-> u32 key (exact round-trip)
__device__ __forceinline__ unsigned fkey(float f) {
    unsigned b = __float_as_uint(f);
    return b ^ (((unsigned)((int)b >> 31)) | 0x80000000u);
}
__device__ __forceinline__ unsigned key_bits(unsigned k) {  // float bits of funkey(k)
    return k ^ (((unsigned)((int)(~k) >> 31)) | 0x80000000u);
}
__device__ __forceinline__ unsigned long long pack2(float x, float y) {
    unsigned long long r; asm("mov.b64 %0,{%1,%2};" : "=l"(r) : "f"(x), "f"(y)); return r;
}
__device__ __forceinline__ void unpack2(unsigned long long v, float& x, float& y) {
    asm("mov.b64 {%0,%1},%2;" : "=f"(x), "=f"(y) : "l"(v));
}
// two independent round-to-nearest f32 adds in one instruction (bit-exact per lane)
__device__ __forceinline__ unsigned long long add2(unsigned long long a, unsigned long long b) {
    unsigned long long r; asm("add.rn.f32x2 %0,%1,%2;" : "=l"(r) : "l"(a), "l"(b)); return r;
}
// pack (key:high32, payload:low32); u64 min == (min key, then min payload)
__device__ __forceinline__ unsigned long long packkj(unsigned key, unsigned p) {
    unsigned long long r; asm("mov.b64 %0,{%1,%2};" : "=l"(r) : "r"(p), "r"(key)); return r;
}
__device__ __forceinline__ unsigned long long umin64(unsigned long long a, unsigned long long b) {
    return a < b ? a : b;
}

__global__ __launch_bounds__(256)
void detr_criterion_kernel(const float* __restrict__ pred_boxes,
                           const float* __restrict__ pred_classes,
                           const float* __restrict__ targets,
                           float* __restrict__ out)
{
    __shared__ __align__(16) float cost[TT * NP];   // [t][n], padded cols zeroed
    __shared__ __align__(16) float4 pb4[NQ];
    __shared__ __align__(16) float4 tg4[TT];
    __shared__ __align__(16) float vneg[NP];        // -v[j]; pads = +1e30 (mask)
    __shared__ __align__(16) float spcfro[NP];      // frozen spc at selection
    __shared__ __align__(16) int2  nxt[NP];         // {path[j], pre-chase col4row[path[j]]}
    __shared__ __align__(16) int   row4col[NQ];
    __shared__ __align__(16) unsigned long long unq[TT];  // {-u[t], -u[t]} packed
    __shared__ float corr[NQ];                      // clip(log1p)-clip(logp) per query
    __shared__ float u[TT];
    __shared__ int   col4row[TT];
    __shared__ int   sorted_idx[TT];
    __shared__ __align__(64) unsigned long long wbest[16];  // 2 parities x 8 slots
    __shared__ float basewarp[8];
    __shared__ float corrs[TT];
    __shared__ float l1s[TT];
    __shared__ float gis[TT];
    __shared__ int   s_last;

    const int b   = blockIdx.x;
    const int tid = threadIdx.x;
    const float* pbg = pred_boxes   + (size_t)b * NQ * 4;
    const float* pc  = pred_classes + (size_t)b * NQ;
    const float* tgg = targets      + (size_t)b * TT * 4;

    // ---- stage boxes in shared (coalesced) + BCE precompute
    for (int n = tid; n < NQ; n += blockDim.x) pb4[n] = ((const float4*)pbg)[n];
    if (tid < TT) tg4[tid] = ((const float4*)tgg)[tid];
    {
        float local_base = 0.0f;
        for (int n = tid; n < NQ; n += blockDim.x) {
            float p = pc[n];
            float lgp = fmaxf(logf(p), -100.0f);
            float lg1 = fmaxf(logf(1.0f - p), -100.0f);
            corr[n] = lg1 - lgp;          // matched correction
            local_base += -lg1;           // unmatched base term
        }
        #pragma unroll
        for (int off = 16; off; off >>= 1)
            local_base += __shfl_down_sync(0xffffffffu, local_base, off);
        if ((tid & 31) == 0) basewarp[tid >> 5] = local_base;
    }
    __syncthreads();

    // ---- cost matrix (padded): cost[t][n] = -pc[n] - giou + L1
    for (int idx = tid; idx < TT * NP; idx += blockDim.x) {
        int t = idx / NP, n = idx - t * NP;
        float cv = 0.0f;
        if (n < NQ) {
            float4 p = pb4[n];
            float4 g = tg4[t];
            float ax0 = p.x, ay0 = p.y, ax1 = p.x + p.z, ay1 = p.y + p.w;
            float bx0 = g.x, by0 = g.y, bx1 = g.x + g.z, by1 = g.y + g.w;
            float area_a = (ax1 - ax0) * (ay1 - ay0);
            float area_b = (bx1 - bx0) * (by1 - by0);
            float iw = fmaxf(fminf(ax1, bx1) - fmaxf(ax0, bx0), 0.0f);
            float ih = fmaxf(fminf(ay1, by1) - fmaxf(ay0, by0), 0.0f);
            float inter = iw * ih;
            float uni = area_a + area_b - inter;
            float iou = inter / uni;
            float cw = fmaxf(fmaxf(ax1, bx1) - fminf(ax0, bx0), 0.0f);
            float ch = fmaxf(fmaxf(ay1, by1) - fminf(ay0, by0), 0.0f);
            float areac = cw * ch;
            float giou = iou - (areac - uni) / areac;
            float l1 = fabsf(p.x - g.x) + fabsf(p.y - g.y) + fabsf(p.z - g.z) + fabsf(p.w - g.w);
            cv = -pc[n] - giou + l1;
        }
        cost[idx] = cv;
    }
    for (int j = tid; j < NP; j += blockDim.x) vneg[j] = (j < NQ) ? 0.0f : HUGEF;
    for (int j = tid; j < NQ; j += blockDim.x) row4col[j] = -1;
    if (tid < TT) { u[tid] = 0.0f; col4row[tid] = -1; unq[tid] = pack2(-0.0f, -0.0f); }
    if (tid < 16) wbest[tid] = 0xFFFFFFFFFFFFFFFFull;   // pad slots stay max forever
    __syncthreads();

    // ---- Hungarian: all 8 warps run loop control; threads 0..159 scan (1 pair each)
    {
        const int lane = tid & 31;
        const int wid  = tid >> 5;
        const unsigned FULL = 0xffffffffu;
        const unsigned KBIG = fkey(BIGF);
        const unsigned HUGEB = __float_as_uint(HUGEF);
        const bool scanner = (tid < NH);
        const bool haveJ   = (2 * tid < NQ);   // tid < 150: real columns
        int par = 0;                           // wbest parity (uniform)

        for (int row = 0; row < TT; ++row) {
            // ---- prologue (reads guarded by the chase barrier of previous row)
            unsigned long long av2 = 0;   // packed -v pair; half -> +1e30 once SC'd
            unsigned spk0 = KBIG, spk1 = KBIG;
            int pth0 = 0, pth1 = 0;
            unsigned jr0 = 0, jr1 = 0;    // payload: (j<<5) | (row4col[j]+1)
            unsigned long long best01 = 0xFFFFFFFFFFFFFFFFull;
            int c4r_cache = 0;            // pre-chase col4row[tid] for dual-u
            if (scanner) {
                av2 = *(const unsigned long long*)&vneg[2 * tid];
                int r0 = -1, r1 = -1;
                if (haveJ) { r0 = row4col[2 * tid]; r1 = row4col[2 * tid + 1]; }
                jr0 = ((unsigned)(2 * tid)     << 5) | (unsigned)(r0 + 1);
                jr1 = ((unsigned)(2 * tid + 1) << 5) | (unsigned)(r1 + 1);
                best01 = umin64(packkj(KBIG, jr0), packkj(KBIG, jr1));
            }
            if (tid < TT) c4r_cache = col4row[tid];
            unsigned SRmask = 0;
            int   cur_i  = row;
            unsigned long long mv2 = 0;               // pack2(0,0) (0.0f bits = 0)
            unsigned long long nu2 = unq[row];        // {-u[row], -u[row]}
            float minVal = 0.0f;
            int   sink   = -1;

            while (sink < 0) {
                SRmask |= 1u << cur_i;
                if (scanner) {
                    const unsigned long long* crowu =
                        (const unsigned long long*)(cost + cur_i * NP);
                    // EXACT ref rounding: ((minVal + c) - u) - v
                    unsigned long long r2 = add2(add2(add2(crowu[tid], mv2), nu2), av2);
                    float rx, ry; unpack2(r2, rx, ry);
                    unsigned kx = fkey(rx), ky = fkey(ry);
                    // critical path: pack this iter's candidates straight into best01
                    best01 = umin64(best01, umin64(packkj(kx, jr0), packkj(ky, jr1)));
                    unsigned bk = (unsigned)(best01 >> 32), bp = (unsigned)best01;
                    // off-critical bookkeeping for duals/path
                    if (kx < spk0) { spk0 = kx; pth0 = cur_i; }
                    if (ky < spk1) { spk1 = ky; pth1 = cur_i; }
                    // per-warp argmin, first-index ties (j in payload bits 5-13, unique)
                    unsigned kw_ = __reduce_min_sync(FULL, bk);
                    unsigned jc  = (bk == kw_) ? bp : 0xffffffffu;
                    unsigned jw  = __reduce_min_sync(FULL, jc);
                    if (lane == 0) wbest[par * 8 + wid] = packkj(kw_, jw);
                }
                __syncthreads();
                ulonglong2 w01 = *(const ulonglong2*)&wbest[par * 8];
                ulonglong2 w23 = *(const ulonglong2*)&wbest[par * 8 + 2];
                ulonglong2 w45 = *(const ulonglong2*)&wbest[par * 8 + 4];  // .y = pad(max)
                unsigned long long g = umin64(umin64(umin64(w01.x, w01.y),
                                                     umin64(w23.x, w23.y)),
                                              umin64(w45.x, w45.y));
                par ^= 1;
                unsigned kmin = (unsigned)(g >> 32);
                unsigned pay  = (unsigned)g;
                unsigned jmin = pay >> 5;
                unsigned rp1  = pay & 31u;
                unsigned mbits = key_bits(kmin);       // exact float bits of minVal
                mv2 = packkj(mbits, mbits);
                minVal = __uint_as_float(mbits);

                spcfro[jmin] = minVal;                 // all threads, same value

                // freeze column jmin (owner thread only) + capture its chase link:
                // at pop time path[jmin] (=pth) is FINAL; col4row is stable in-search.
                if (tid == (int)(jmin >> 1)) {
                    int psel;
                    if (jmin & 1u) {
                        psel = pth1;
                        spk1 = KBIG;
                        av2 = (av2 & 0x00000000FFFFFFFFull) | ((unsigned long long)HUGEB << 32);
                    } else {
                        psel = pth0;
                        spk0 = KBIG;
                        av2 = (av2 & 0xFFFFFFFF00000000ull) | (unsigned long long)HUGEB;
                    }
                    best01 = umin64(packkj(spk0, jr0), packkj(spk1, jr1));
                    nxt[jmin] = make_int2(psel, col4row[psel]);
                }

                if (rp1 == 0u) sink = (int)jmin;
                else { cur_i = (int)rp1 - 1; nu2 = unq[cur_i]; }
            }
            __syncthreads();   // all in-loop nxt/spcfro writes visible

            // ---- merged interval: dual updates (all) ∥ chase (thread 0); disjoint state
            if (scanner) {
                float ax, ay; unpack2(av2, ax, ay); int j0 = 2 * tid;
                if (j0     < NQ && ax == HUGEF) vneg[j0]     += minVal - spcfro[j0];
                if (j0 + 1 < NQ && ay == HUGEF) vneg[j0 + 1] += minVal - spcfro[j0 + 1];
            }
            if (tid < TT) {
                if (tid == row) u[tid] += minVal;
                else if ((SRmask >> tid) & 1u) u[tid] += minVal - spcfro[c4r_cache];
                unq[tid] = pack2(-u[tid], -u[tid]);
            }
            if (tid == 0) {
                // augment along alternating path (uses pre-captured nxt links)
                int j = sink;
                for (;;) {
                    int2 e = nxt[j];
                    row4col[j] = e.x;
                    col4row[e.x] = j;
                    if (e.x == row) break;
                    j = e.y;
                }
            }
            __syncthreads();   // duals + matching visible for next prologue
        }

        // boxes_idx = sort(col4row)
        if (tid == 0) {
            for (int i = 0; i < TT; ++i) sorted_idx[i] = col4row[i];
            for (int i = 1; i < TT; ++i) {
                int key = sorted_idx[i];
                int k = i - 1;
                while (k >= 0 && sorted_idx[k] > key) { sorted_idx[k + 1] = sorted_idx[k]; --k; }
                sorted_idx[k + 1] = key;
            }
        }
    }
    __syncthreads();

    // ---- L1 + GIoU on matched (sorted-index) pairs; BCE corrections
    if (tid < TT) {
        int t = tid;
        int n = sorted_idx[t];
        corrs[t] = corr[n];
        float4 p = pb4[n];
        float4 g = tg4[t];
        l1s[t] = fabsf(p.x - g.x) + fabsf(p.y - g.y) + fabsf(p.z - g.z) + fabsf(p.w - g.w);

        float ax0 = p.x, ay0 = p.y, ax1 = p.x + p.z, ay1 = p.y + p.w;
        float bx0 = g.x, by0 = g.y, bx1 = g.x + g.z, by1 = g.y + g.w;
        float area_a = (ax1 - ax0) * (ay1 - ay0);
        float area_b = (bx1 - bx0) * (by1 - by0);
        float iw = fmaxf(fminf(ax1, bx1) - fmaxf(ax0, bx0), 0.0f);
        float ih = fmaxf(fminf(ay1, by1) - fmaxf(ay0, by0), 0.0f);
        float inter = iw * ih;
        float uni = area_a + area_b - inter;
        float iou = inter / uni;
        float cw = fmaxf(fmaxf(ax1, bx1) - fminf(ax0, bx0), 0.0f);
        float ch = fmaxf(fmaxf(ay1, by1) - fminf(ay0, by0), 0.0f);
        float areac = cw * ch;
        float giou = iou - (areac - uni) / areac;
        gis[t] = 1.0f - giou;
    }
    __syncthreads();

    // ---- per-batch partials + last-block final reduction (deterministic order)
    if (tid == 0) {
        float bce = 0.0f;
        #pragma unroll
        for (int w = 0; w < 8; ++w) bce += basewarp[w];
        for (int t = 0; t < TT; ++t) bce += corrs[t];
        float l1 = 0.0f, gi = 0.0f;
        for (int t = 0; t < TT; ++t) { l1 += l1s[t]; gi += gis[t]; }
        g_partials[b * 3 + 0] = bce;
        g_partials[b * 3 + 1] = l1;
        g_partials[b * 3 + 2] = gi;
        __threadfence();
        unsigned ticket = atomicAdd(&g_count, 1u);
        s_last = (ticket == BB - 1) ? 1 : 0;
    }
    __syncthreads();

    if (s_last) {
        __threadfence();
        if (tid < 3) {
            float s = 0.0f;
            for (int bb2 = 0; bb2 < BB; ++bb2) s += g_partials[bb2 * 3 + tid];
            float denom = (tid == 0) ? (float)(BB * NQ) : (float)(BB * TT);
            out[tid] = s / denom;
        }
        if (tid == 0) g_count = 0;   // reset for next graph replay
    }
}

extern "C" void kernel_launch(void* const* d_in, const int* in_sizes, int n_in,
                              void* d_out, int out_size)
{
    const float* pred_boxes = nullptr;
    const float* pred_classes = nullptr;
    const float* targets = nullptr;
    for (int i = 0; i < n_in; ++i) {
        if (in_sizes[i] == BB * NQ * 4)      pred_boxes   = (const float*)d_in[i];
        else if (in_sizes[i] == BB * NQ)     pred_classes = (const float*)d_in[i];
        else if (in_sizes[i] == BB * TT * 4) targets      = (const float*)d_in[i];
    }
    detr_criterion_kernel<<<BB, 256>>>(pred_boxes, pred_classes, targets, (float*)d_out);
}